// round 15
// baseline (speedup 1.0000x reference)
#include <cuda_runtime.h>
#include <cuda_bf16.h>
#include <mma.h>
#include <cstdint>

using namespace nvcuda;

#define T_SEQ 512
#define B_SZ  256
#define IN_D  64
#define H_D   128
#define G4    512
#define TB    (T_SEQ * B_SZ)
#define TC    64                      // timesteps per chunk (R13-good)
#define NCH   8                       // chunks (R13-good)
#define CHROWS (TC * B_SZ)            // 16384 rows per chunk

// ---- scratch (__device__ globals) ----
__device__ float g_bufA[TB * H_D];                    // f32 sink
__device__ float g_preb[5ULL * TB * G4];              // per-layer pre
__device__ __nv_bfloat16 g_actH[5ULL * TB * H_D];     // per-layer h hi
__device__ __nv_bfloat16 g_actL[5ULL * TB * H_D];     // per-layer h lo
__device__ __nv_bfloat16 g_xh[TB * IN_D];
__device__ __nv_bfloat16 g_xl[TB * IN_D];
__device__ __nv_bfloat16 g_wh[5 * H_D * G4];          // per-layer W^T hi
__device__ __nv_bfloat16 g_wl[5 * H_D * G4];
__device__ float g_hst[5 * B_SZ * H_D];               // h carry
__device__ float g_cst[5 * B_SZ * H_D];               // c carry

// ---------------- helpers ----------------
__device__ __forceinline__ void fma2(unsigned long long &acc,
                                     unsigned long long a, unsigned long long b) {
    asm("fma.rn.f32x2 %0, %1, %2, %3;" : "=l"(acc) : "l"(a), "l"(b), "l"(acc));
}
__device__ __forceinline__ unsigned long long pack2(float lo, float hi) {
    unsigned long long r;
    asm("mov.b64 %0, {%1, %2};" : "=l"(r) : "f"(lo), "f"(hi));
    return r;
}
__device__ __forceinline__ float sum2(unsigned long long v) {
    float lo, hi;
    asm("mov.b64 {%0, %1}, %2;" : "=f"(lo), "=f"(hi) : "l"(v));
    return lo + hi;
}
__device__ __forceinline__ float fsig(float x) {
    return __fdividef(1.0f, 1.0f + __expf(-x));
}
__device__ __forceinline__ float ftanh(float x) {
    return __fdividef(2.0f, 1.0f + __expf(-2.0f * x)) - 1.0f;
}
__device__ __forceinline__ void split2(float a, float b,
                                       __nv_bfloat162 &h, __nv_bfloat162 &l) {
    const __nv_bfloat16 ha = __float2bfloat16_rn(a);
    const __nv_bfloat16 hb = __float2bfloat16_rn(b);
    h.x = ha; h.y = hb;
    l.x = __float2bfloat16_rn(a - __bfloat162float(ha));
    l.y = __float2bfloat16_rn(b - __bfloat162float(hb));
}

// ============================================================================
__global__ void xconvert(const float* __restrict__ x,
                         __nv_bfloat16* __restrict__ xh,
                         __nv_bfloat16* __restrict__ xl, int n4) {
    const int i = blockIdx.x * blockDim.x + threadIdx.x;
    if (i >= n4) return;
    const float4 v = ((const float4*)x)[i];
    __nv_bfloat162 h0, l0, h1, l1;
    split2(v.x, v.y, h0, l0);
    split2(v.z, v.w, h1, l1);
    ((__nv_bfloat162*)xh)[2 * i]     = h0;
    ((__nv_bfloat162*)xh)[2 * i + 1] = h1;
    ((__nv_bfloat162*)xl)[2 * i]     = l0;
    ((__nv_bfloat162*)xl)[2 * i + 1] = l1;
}

__global__ void wconvert(const float* __restrict__ W,
                         __nv_bfloat16* __restrict__ wh,
                         __nv_bfloat16* __restrict__ wl, int K) {
    const int e = blockIdx.x * blockDim.x + threadIdx.x;
    if (e >= K * G4) return;
    const int k = e >> 9, n = e & 511;
    const float v = W[(size_t)n * K + k];
    const __nv_bfloat16 h = __float2bfloat16_rn(v);
    wh[e] = h;
    wl[e] = __float2bfloat16_rn(v - __bfloat162float(h));
}

// ============================================================================
// pregemm (measured-good), chunked. grid per chunk = (CHROWS/64)*4 = 1024.
// ============================================================================
template<int K>
__global__ void __launch_bounds__(256, 2)
pregemm(const __nv_bfloat16* __restrict__ Ahg,
        const __nv_bfloat16* __restrict__ Alg,
        const __nv_bfloat16* __restrict__ Bhg,
        const __nv_bfloat16* __restrict__ Blg,
        const float* __restrict__ bih, const float* __restrict__ bhh,
        float* __restrict__ pre)
{
    constexpr int AS = K + 8;
    constexpr int BS = 128 + 8;
    extern __shared__ __align__(256) char smp[];
    float* bias = (float*)smp;
    __nv_bfloat16* Ah = (__nv_bfloat16*)(smp + 512);
    __nv_bfloat16* Al = Ah + 64 * AS;
    __nv_bfloat16* Bh = Al + 64 * AS;
    __nv_bfloat16* Bl = Bh + K * BS;
    float* Dsm = (float*)(smp + 512);

    const int tid = threadIdx.x;
    const int wid = tid >> 5;
    const int m0 = (int)(blockIdx.x >> 2) * 64;
    const int n0 = (int)(blockIdx.x & 3) * 128;

    if (tid < 128) bias[tid] = bih[n0 + tid] + bhh[n0 + tid];

    for (int i = tid; i < 64 * K / 8; i += 256) {
        const int r = i / (K / 8), c8 = (i % (K / 8)) * 8;
        *(uint4*)(Ah + r * AS + c8) =
            *(const uint4*)(Ahg + (size_t)(m0 + r) * K + c8);
        *(uint4*)(Al + r * AS + c8) =
            *(const uint4*)(Alg + (size_t)(m0 + r) * K + c8);
    }
    for (int i = tid; i < K * 16; i += 256) {
        const int k = i >> 4, c8 = (i & 15) * 8;
        *(uint4*)(Bh + k * BS + c8) =
            *(const uint4*)(Bhg + (size_t)k * G4 + n0 + c8);
        *(uint4*)(Bl + k * BS + c8) =
            *(const uint4*)(Blg + (size_t)k * G4 + n0 + c8);
    }
    __syncthreads();

    const int wm = wid >> 1;
    const int wn = wid & 1;

    wmma::fragment<wmma::accumulator, 16, 16, 16, float> acc[4];
#pragma unroll
    for (int ni = 0; ni < 4; ni++) wmma::fill_fragment(acc[ni], 0.0f);

#pragma unroll
    for (int ks = 0; ks < K / 16; ks++) {
        wmma::fragment<wmma::matrix_a, 16, 16, 16, __nv_bfloat16,
                       wmma::row_major> ah, al;
        wmma::load_matrix_sync(ah, Ah + (wm * 16) * AS + ks * 16, AS);
        wmma::load_matrix_sync(al, Al + (wm * 16) * AS + ks * 16, AS);
#pragma unroll
        for (int ni = 0; ni < 4; ni++) {
            wmma::fragment<wmma::matrix_b, 16, 16, 16, __nv_bfloat16,
                           wmma::row_major> bhf, blf;
            wmma::load_matrix_sync(bhf,
                Bh + ks * 16 * BS + wn * 64 + ni * 16, BS);
            wmma::load_matrix_sync(blf,
                Bl + ks * 16 * BS + wn * 64 + ni * 16, BS);
            wmma::mma_sync(acc[ni], ah, bhf, acc[ni]);
            wmma::mma_sync(acc[ni], ah, blf, acc[ni]);
            wmma::mma_sync(acc[ni], al, bhf, acc[ni]);
        }
    }
    __syncthreads();

#pragma unroll
    for (int ni = 0; ni < 4; ni++)
        wmma::store_matrix_sync(
            Dsm + (wm * 16) * 128 + wn * 64 + ni * 16,
            acc[ni], 128, wmma::mem_row_major);
    __syncthreads();

    for (int i = tid; i < 64 * 32; i += 256) {
        const int r = i >> 5, c4 = (i & 31) * 4;
        float4 v = *(const float4*)(Dsm + r * 128 + c4);
        v.x += bias[c4];     v.y += bias[c4 + 1];
        v.z += bias[c4 + 2]; v.w += bias[c4 + 3];
        *(float4*)(pre + (size_t)(m0 + r) * G4 + n0 + c4) = v;
    }
}

// ============================================================================
// lstm_rec chunk, QUARTER-FOOTPRINT: 64 CTAs x 256 threads, cluster of 4,
// 16 batch rows per cluster (4 dot passes of 4 rows). Same validated
// own/peer + barrier.cluster skeleton. 4 layers' rec kernels co-reside
// (4 x 64 = 256 CTAs <= 296 slots). gbuf+hs in dynamic smem (80KB).
// Epilogue: each of 256 threads owns 2 cells (rows ob and ob+8).
// ============================================================================
#define DSMREC ((8 * 16 * 128 + 2 * 16 * 128) * 4)   // 81920 B

__global__ void __launch_bounds__(256, 2) __cluster_dims__(4, 1, 1)
lstm_rec(const float* __restrict__ pre,   // chunk base [TC,B,512]
         float* __restrict__ out,         // chunk base [TC,B,128]
         const float* __restrict__ Whh,   // [512,128]
         __nv_bfloat16* __restrict__ gh,
         __nv_bfloat16* __restrict__ gl,
         float* __restrict__ hst,         // [B,128] carry
         float* __restrict__ cst,         // [B,128] carry
         int first)
{
    extern __shared__ __align__(16) float dsm[];
    float* gbuf = dsm;                       // [8][16][128]
    float* hsm  = dsm + 8 * 16 * 128;        // [2][16][128]

    const int tid = threadIdx.x, lane = tid & 31, w = tid >> 5;
    uint32_t rank;
    asm("mov.u32 %0, %%cluster_ctarank;" : "=r"(rank));
    const int sl = (w + 2 * (int)rank) & 7;
    const int k0 = sl * 16;
    const bool own = (w < 2);
    const int b0 = (blockIdx.x >> 2) * 16;   // 16 rows per cluster

    unsigned long long Wr[4][8];
#pragma unroll
    for (int g = 0; g < 4; g++) {
        const int grow = g * H_D + (int)rank * 32 + lane;
#pragma unroll
        for (int i = 0; i < 8; i++)
            Wr[g][i] = pack2(Whh[grow * H_D + k0 + 2 * i],
                             Whh[grow * H_D + k0 + 2 * i + 1]);
    }

    // epilogue identity: thread owns cells (ob, oj) and (ob+8, oj)
    const int ob = tid >> 5, oj = tid & 31;
    const int jglob = (int)rank * 32 + oj;
    float cs0 = 0.0f, cs1 = 0.0f;
    const float* pre_p0 = pre + ((size_t)b0 + ob)     * G4 + jglob;
    const float* pre_p1 = pre + ((size_t)b0 + ob + 8) * G4 + jglob;
    float* out_p0 = out + ((size_t)b0 + ob)     * H_D + jglob;
    float* out_p1 = out + ((size_t)b0 + ob + 8) * H_D + jglob;
    __nv_bfloat16* gh_p0 = gh + ((size_t)b0 + ob)     * H_D + jglob;
    __nv_bfloat16* gh_p1 = gh + ((size_t)b0 + ob + 8) * H_D + jglob;
    __nv_bfloat16* gl_p0 = gl + ((size_t)b0 + ob)     * H_D + jglob;
    __nv_bfloat16* gl_p1 = gl + ((size_t)b0 + ob + 8) * H_D + jglob;

    if (first) {
        for (int i = tid; i < 16 * H_D; i += 256) hsm[i] = 0.0f;
    } else {
        for (int i = tid; i < 16 * H_D; i += 256)
            hsm[i] = hst[(size_t)(b0 + (i >> 7)) * H_D + (i & 127)];
        cs0 = cst[(size_t)(b0 + ob)     * H_D + jglob];
        cs1 = cst[(size_t)(b0 + ob + 8) * H_D + jglob];
    }
    __syncthreads();
    asm volatile("barrier.cluster.arrive.aligned;" ::: "memory");

    for (int tl = 0; tl < TC; tl++) {
        const int cur = tl & 1, nxt = cur ^ 1;
        const bool more = (tl + 1 < TC);

        const float pa0 = pre_p0[0],   pa1 = pre_p0[128];
        const float pa2 = pre_p0[256], pa3 = pre_p0[384];
        const float pb0 = pre_p1[0],   pb1 = pre_p1[128];
        const float pb2 = pre_p1[256], pb3 = pre_p1[384];
        pre_p0 += (size_t)B_SZ * G4;
        pre_p1 += (size_t)B_SZ * G4;

        if (own) {   // local h columns (ordered by trailing __syncthreads)
#pragma unroll
            for (int pass = 0; pass < 4; pass++) {
                unsigned long long acc[4][4];
#pragma unroll
                for (int g = 0; g < 4; g++)
#pragma unroll
                    for (int b = 0; b < 4; b++) acc[g][b] = 0ull;
#pragma unroll
                for (int kk = 0; kk < 4; kk++) {
                    ulonglong2 v[4];
#pragma unroll
                    for (int b = 0; b < 4; b++)
                        v[b] = *(const ulonglong2*)(
                            &hsm[(cur * 16 + pass * 4 + b) * 128 + k0 + 4 * kk]);
#pragma unroll
                    for (int g = 0; g < 4; g++)
#pragma unroll
                        for (int b = 0; b < 4; b++) {
                            fma2(acc[g][b], v[b].x, Wr[g][2 * kk]);
                            fma2(acc[g][b], v[b].y, Wr[g][2 * kk + 1]);
                        }
                }
#pragma unroll
                for (int g = 0; g < 4; g++)
#pragma unroll
                    for (int b = 0; b < 4; b++)
                        gbuf[(sl * 16 + pass * 4 + b) * 128 + g * 32 + lane] =
                            sum2(acc[g][b]);
            }
        }

        asm volatile("barrier.cluster.wait.aligned;" ::: "memory");

        if (!own) {  // peer h columns (DSMEM-published before the barrier)
#pragma unroll
            for (int pass = 0; pass < 4; pass++) {
                unsigned long long acc[4][4];
#pragma unroll
                for (int g = 0; g < 4; g++)
#pragma unroll
                    for (int b = 0; b < 4; b++) acc[g][b] = 0ull;
#pragma unroll
                for (int kk = 0; kk < 4; kk++) {
                    ulonglong2 v[4];
#pragma unroll
                    for (int b = 0; b < 4; b++)
                        v[b] = *(const ulonglong2*)(
                            &hsm[(cur * 16 + pass * 4 + b) * 128 + k0 + 4 * kk]);
#pragma unroll
                    for (int g = 0; g < 4; g++)
#pragma unroll
                        for (int b = 0; b < 4; b++) {
                            fma2(acc[g][b], v[b].x, Wr[g][2 * kk]);
                            fma2(acc[g][b], v[b].y, Wr[g][2 * kk + 1]);
                        }
                }
#pragma unroll
                for (int g = 0; g < 4; g++)
#pragma unroll
                    for (int b = 0; b < 4; b++)
                        gbuf[(sl * 16 + pass * 4 + b) * 128 + g * 32 + lane] =
                            sum2(acc[g][b]);
            }
        }

        __syncthreads();

        // ---- epilogue: 2 cells per thread ----
#pragma unroll
        for (int half = 0; half < 2; half++) {
            const int row = ob + half * 8;
            float gv0 = half ? pb0 : pa0;
            float gv1 = half ? pb1 : pa1;
            float gv2 = half ? pb2 : pa2;
            float gv3 = half ? pb3 : pa3;
#pragma unroll
            for (int q = 0; q < 8; q++) {
                const float* gb = &gbuf[(q * 16 + row) * 128];
                gv0 += gb[oj];
                gv1 += gb[32 + oj];
                gv2 += gb[64 + oj];
                gv3 += gb[96 + oj];
            }
            const float ig = fsig(gv0), fg = fsig(gv1);
            const float gg = ftanh(gv2), og = fsig(gv3);
            float &cs = half ? cs1 : cs0;
            cs = fg * cs + ig * gg;
            const float h = og * ftanh(cs);

            if (more) {
                float* hp = &hsm[(nxt * 16 + row) * 128 + jglob];
                *hp = h;
                const uint32_t la = (uint32_t)__cvta_generic_to_shared(hp);
#pragma unroll
                for (int pr = 0; pr < 4; pr++)
                    if (pr != (int)rank)
                        asm volatile("{ .reg .b32 ra;\n\t"
                            "mapa.shared::cluster.u32 ra, %0, %1;\n\t"
                            "st.shared::cluster.f32 [ra], %2; }"
                            :: "r"(la), "r"(pr), "f"(h) : "memory");
            } else {
                hst[(size_t)(b0 + row) * H_D + jglob] = h;
                cst[(size_t)(b0 + row) * H_D + jglob] = cs;
            }
            if (half) {
                *out_p1 = h;  out_p1 += (size_t)B_SZ * H_D;
                const __nv_bfloat16 hh = __float2bfloat16_rn(h);
                *gh_p1 = hh;
                *gl_p1 = __float2bfloat16_rn(h - __bfloat162float(hh));
                gh_p1 += (size_t)B_SZ * H_D;  gl_p1 += (size_t)B_SZ * H_D;
            } else {
                *out_p0 = h;  out_p0 += (size_t)B_SZ * H_D;
                const __nv_bfloat16 hh = __float2bfloat16_rn(h);
                *gh_p0 = hh;
                *gl_p0 = __float2bfloat16_rn(h - __bfloat162float(hh));
                gh_p0 += (size_t)B_SZ * H_D;  gl_p0 += (size_t)B_SZ * H_D;
            }
        }

        if (more)
            asm volatile("barrier.cluster.arrive.aligned;" ::: "memory");
        __syncthreads();
    }
}

// ============================================================================
// stream/event DAG (R13 config: same-priority streams)
// ============================================================================
struct DagRes {
    cudaStream_t ls[5], lp[5];
    cudaEvent_t fork, evP[5][NCH], evR[5][NCH], tail[10];
    DagRes() {
        for (int l = 0; l < 5; l++) {
            cudaStreamCreateWithFlags(&ls[l], cudaStreamNonBlocking);
            cudaStreamCreateWithFlags(&lp[l], cudaStreamNonBlocking);
        }
        cudaEventCreateWithFlags(&fork, cudaEventDisableTiming);
        for (int l = 0; l < 5; l++)
            for (int c = 0; c < NCH; c++) {
                cudaEventCreateWithFlags(&evP[l][c], cudaEventDisableTiming);
                cudaEventCreateWithFlags(&evR[l][c], cudaEventDisableTiming);
            }
        for (int i = 0; i < 10; i++)
            cudaEventCreateWithFlags(&tail[i], cudaEventDisableTiming);
    }
};
static DagRes g_dag;

extern "C" void kernel_launch(void* const* d_in, const int* in_sizes, int n_in,
                              void* d_out, int out_size) {
    const float* x     = (const float*)d_in[0];
    const float* Wih0  = (const float*)d_in[1];
    const float* Wrest = (const float*)d_in[2];
    const float* Whh   = (const float*)d_in[3];
    const float* bih   = (const float*)d_in[4];
    const float* bhh   = (const float*)d_in[5];
    float* out = (float*)d_out;

    float *bufA, *preb, *hst, *cst;
    __nv_bfloat16 *actH, *actL, *xh, *xl, *wh, *wl;
    cudaGetSymbolAddress((void**)&bufA, g_bufA);
    cudaGetSymbolAddress((void**)&preb, g_preb);
    cudaGetSymbolAddress((void**)&actH, g_actH);
    cudaGetSymbolAddress((void**)&actL, g_actL);
    cudaGetSymbolAddress((void**)&xh, g_xh);
    cudaGetSymbolAddress((void**)&xl, g_xl);
    cudaGetSymbolAddress((void**)&wh, g_wh);
    cudaGetSymbolAddress((void**)&wl, g_wl);
    cudaGetSymbolAddress((void**)&hst, g_hst);
    cudaGetSymbolAddress((void**)&cst, g_cst);

    const int SP64  = 512 + 64 * 72  * 2 * 2 + 64  * 136 * 2 * 2;  //  53760
    const int SP128 = 512 + 64 * 136 * 2 * 2 + 128 * 136 * 2 * 2;  // 104960
    cudaFuncSetAttribute(pregemm<64>,
        cudaFuncAttributeMaxDynamicSharedMemorySize, SP64);
    cudaFuncSetAttribute(pregemm<128>,
        cudaFuncAttributeMaxDynamicSharedMemorySize, SP128);
    cudaFuncSetAttribute(lstm_rec,
        cudaFuncAttributeMaxDynamicSharedMemorySize, DSMREC);

    DagRes& D = g_dag;

    // ---- upfront conversions on the capture stream ----
    xconvert<<<TB * IN_D / 4 / 256, 256>>>(x, xh, xl, TB * IN_D / 4);
    wconvert<<<64 * G4 / 256, 256>>>(Wih0, wh, wl, 64);
    for (int l = 1; l < 5; l++)
        wconvert<<<128 * G4 / 256, 256>>>(
            Wrest + (size_t)(l - 1) * G4 * H_D,
            wh + (size_t)l * H_D * G4, wl + (size_t)l * H_D * G4, 128);

    cudaEventRecord(D.fork, 0);
    for (int l = 0; l < 5; l++) {
        cudaStreamWaitEvent(D.lp[l], D.fork, 0);
        cudaStreamWaitEvent(D.ls[l], D.fork, 0);
    }

    // ---- pipelined layer-chunk DAG ----
    for (int c = 0; c < NCH; c++) {
        for (int l = 0; l < 5; l++) {
            const size_t rowoff = (size_t)c * CHROWS;
            float* pre_c = preb + ((size_t)l * TB + rowoff) * G4;

            if (l > 0) cudaStreamWaitEvent(D.lp[l], D.evR[l - 1][c], 0);
            if (l == 0) {
                pregemm<64><<<CHROWS / 64 * 4, 256, SP64, D.lp[0]>>>(
                    xh + rowoff * IN_D, xl + rowoff * IN_D,
                    wh, wl, bih, bhh, pre_c);
            } else {
                const size_t aoff = ((size_t)(l - 1) * TB + rowoff) * H_D;
                pregemm<128><<<CHROWS / 64 * 4, 256, SP128, D.lp[l]>>>(
                    actH + aoff, actL + aoff,
                    wh + (size_t)l * H_D * G4, wl + (size_t)l * H_D * G4,
                    bih + (size_t)l * G4, bhh + (size_t)l * G4, pre_c);
            }
            cudaEventRecord(D.evP[l][c], D.lp[l]);

            cudaStreamWaitEvent(D.ls[l], D.evP[l][c], 0);
            float* out_c = (l == 4) ? out + rowoff * H_D
                                    : bufA + rowoff * H_D;
            const size_t goff = ((size_t)l * TB + rowoff) * H_D;
            lstm_rec<<<64, 256, DSMREC, D.ls[l]>>>(
                pre_c, out_c, Whh + (size_t)l * G4 * H_D,
                actH + goff, actL + goff,
                hst + (size_t)l * B_SZ * H_D, cst + (size_t)l * B_SZ * H_D,
                (c == 0) ? 1 : 0);
            cudaEventRecord(D.evR[l][c], D.ls[l]);
        }
    }

    // ---- join all side streams back to the capture stream ----
    for (int l = 0; l < 5; l++) {
        cudaEventRecord(D.tail[l], D.ls[l]);
        cudaStreamWaitEvent(0, D.tail[l], 0);
        cudaEventRecord(D.tail[5 + l], D.lp[l]);
        cudaStreamWaitEvent(0, D.tail[5 + l], 0);
    }
}

// round 16
// speedup vs baseline: 1.0977x; 1.0977x over previous
#include <cuda_runtime.h>
#include <cuda_bf16.h>
#include <mma.h>
#include <cstdint>

using namespace nvcuda;

#define T_SEQ 512
#define B_SZ  256
#define IN_D  64
#define H_D   128
#define G4    512
#define TB    (T_SEQ * B_SZ)
#define TC    64                      // timesteps per chunk (R13-good)
#define NCH   8                       // chunks (R13-good)
#define CHROWS (TC * B_SZ)            // 16384 rows per chunk

// ---- scratch (__device__ globals) ----
__device__ float g_bufA[TB * H_D];                    // f32 sink (unused data)
__device__ float g_preb[5ULL * TB * G4];              // per-layer pre
__device__ __nv_bfloat16 g_actH[5ULL * TB * H_D];     // per-layer h hi
__device__ __nv_bfloat16 g_actL[5ULL * TB * H_D];     // per-layer h lo
__device__ __nv_bfloat16 g_xh[TB * IN_D];
__device__ __nv_bfloat16 g_xl[TB * IN_D];
__device__ __nv_bfloat16 g_wh[5 * H_D * G4];          // per-layer W^T hi
__device__ __nv_bfloat16 g_wl[5 * H_D * G4];
__device__ float g_hst[5 * B_SZ * H_D];               // h carry
__device__ float g_cst[5 * B_SZ * H_D];               // c carry

// ---------------- helpers ----------------
__device__ __forceinline__ void fma2(unsigned long long &acc,
                                     unsigned long long a, unsigned long long b) {
    asm("fma.rn.f32x2 %0, %1, %2, %3;" : "=l"(acc) : "l"(a), "l"(b), "l"(acc));
}
__device__ __forceinline__ unsigned long long pack2(float lo, float hi) {
    unsigned long long r;
    asm("mov.b64 %0, {%1, %2};" : "=l"(r) : "f"(lo), "f"(hi));
    return r;
}
__device__ __forceinline__ float sum2(unsigned long long v) {
    float lo, hi;
    asm("mov.b64 {%0, %1}, %2;" : "=f"(lo), "=f"(hi) : "l"(v));
    return lo + hi;
}
__device__ __forceinline__ float fsig(float x) {
    return __fdividef(1.0f, 1.0f + __expf(-x));
}
__device__ __forceinline__ float ftanh(float x) {
    return __fdividef(2.0f, 1.0f + __expf(-2.0f * x)) - 1.0f;
}
__device__ __forceinline__ void split2(float a, float b,
                                       __nv_bfloat162 &h, __nv_bfloat162 &l) {
    const __nv_bfloat16 ha = __float2bfloat16_rn(a);
    const __nv_bfloat16 hb = __float2bfloat16_rn(b);
    h.x = ha; h.y = hb;
    l.x = __float2bfloat16_rn(a - __bfloat162float(ha));
    l.y = __float2bfloat16_rn(b - __bfloat162float(hb));
}

// ============================================================================
__global__ void xconvert(const float* __restrict__ x,
                         __nv_bfloat16* __restrict__ xh,
                         __nv_bfloat16* __restrict__ xl, int n4) {
    const int i = blockIdx.x * blockDim.x + threadIdx.x;
    if (i >= n4) return;
    const float4 v = ((const float4*)x)[i];
    __nv_bfloat162 h0, l0, h1, l1;
    split2(v.x, v.y, h0, l0);
    split2(v.z, v.w, h1, l1);
    ((__nv_bfloat162*)xh)[2 * i]     = h0;
    ((__nv_bfloat162*)xh)[2 * i + 1] = h1;
    ((__nv_bfloat162*)xl)[2 * i]     = l0;
    ((__nv_bfloat162*)xl)[2 * i + 1] = l1;
}

__global__ void wconvert(const float* __restrict__ W,
                         __nv_bfloat16* __restrict__ wh,
                         __nv_bfloat16* __restrict__ wl, int K) {
    const int e = blockIdx.x * blockDim.x + threadIdx.x;
    if (e >= K * G4) return;
    const int k = e >> 9, n = e & 511;
    const float v = W[(size_t)n * K + k];
    const __nv_bfloat16 h = __float2bfloat16_rn(v);
    wh[e] = h;
    wl[e] = __float2bfloat16_rn(v - __bfloat162float(h));
}

// ============================================================================
// pregemm (measured-good), chunked. grid per chunk = (CHROWS/64)*4 = 1024.
// ============================================================================
template<int K>
__global__ void __launch_bounds__(256, 2)
pregemm(const __nv_bfloat16* __restrict__ Ahg,
        const __nv_bfloat16* __restrict__ Alg,
        const __nv_bfloat16* __restrict__ Bhg,
        const __nv_bfloat16* __restrict__ Blg,
        const float* __restrict__ bih, const float* __restrict__ bhh,
        float* __restrict__ pre)
{
    constexpr int AS = K + 8;
    constexpr int BS = 128 + 8;
    extern __shared__ __align__(256) char smp[];
    float* bias = (float*)smp;
    __nv_bfloat16* Ah = (__nv_bfloat16*)(smp + 512);
    __nv_bfloat16* Al = Ah + 64 * AS;
    __nv_bfloat16* Bh = Al + 64 * AS;
    __nv_bfloat16* Bl = Bh + K * BS;
    float* Dsm = (float*)(smp + 512);

    const int tid = threadIdx.x;
    const int wid = tid >> 5;
    const int m0 = (int)(blockIdx.x >> 2) * 64;
    const int n0 = (int)(blockIdx.x & 3) * 128;

    if (tid < 128) bias[tid] = bih[n0 + tid] + bhh[n0 + tid];

    for (int i = tid; i < 64 * K / 8; i += 256) {
        const int r = i / (K / 8), c8 = (i % (K / 8)) * 8;
        *(uint4*)(Ah + r * AS + c8) =
            *(const uint4*)(Ahg + (size_t)(m0 + r) * K + c8);
        *(uint4*)(Al + r * AS + c8) =
            *(const uint4*)(Alg + (size_t)(m0 + r) * K + c8);
    }
    for (int i = tid; i < K * 16; i += 256) {
        const int k = i >> 4, c8 = (i & 15) * 8;
        *(uint4*)(Bh + k * BS + c8) =
            *(const uint4*)(Bhg + (size_t)k * G4 + n0 + c8);
        *(uint4*)(Bl + k * BS + c8) =
            *(const uint4*)(Blg + (size_t)k * G4 + n0 + c8);
    }
    __syncthreads();

    const int wm = wid >> 1;
    const int wn = wid & 1;

    wmma::fragment<wmma::accumulator, 16, 16, 16, float> acc[4];
#pragma unroll
    for (int ni = 0; ni < 4; ni++) wmma::fill_fragment(acc[ni], 0.0f);

#pragma unroll
    for (int ks = 0; ks < K / 16; ks++) {
        wmma::fragment<wmma::matrix_a, 16, 16, 16, __nv_bfloat16,
                       wmma::row_major> ah, al;
        wmma::load_matrix_sync(ah, Ah + (wm * 16) * AS + ks * 16, AS);
        wmma::load_matrix_sync(al, Al + (wm * 16) * AS + ks * 16, AS);
#pragma unroll
        for (int ni = 0; ni < 4; ni++) {
            wmma::fragment<wmma::matrix_b, 16, 16, 16, __nv_bfloat16,
                           wmma::row_major> bhf, blf;
            wmma::load_matrix_sync(bhf,
                Bh + ks * 16 * BS + wn * 64 + ni * 16, BS);
            wmma::load_matrix_sync(blf,
                Bl + ks * 16 * BS + wn * 64 + ni * 16, BS);
            wmma::mma_sync(acc[ni], ah, bhf, acc[ni]);
            wmma::mma_sync(acc[ni], ah, blf, acc[ni]);
            wmma::mma_sync(acc[ni], al, bhf, acc[ni]);
        }
    }
    __syncthreads();

#pragma unroll
    for (int ni = 0; ni < 4; ni++)
        wmma::store_matrix_sync(
            Dsm + (wm * 16) * 128 + wn * 64 + ni * 16,
            acc[ni], 128, wmma::mem_row_major);
    __syncthreads();

    for (int i = tid; i < 64 * 32; i += 256) {
        const int r = i >> 5, c4 = (i & 31) * 4;
        float4 v = *(const float4*)(Dsm + r * 128 + c4);
        v.x += bias[c4];     v.y += bias[c4 + 1];
        v.z += bias[c4 + 2]; v.w += bias[c4 + 3];
        *(float4*)(pre + (size_t)(m0 + r) * G4 + n0 + c4) = v;
    }
}

// ============================================================================
// lstm_rec chunk (exact R13-measured-good structure): 128 CTAs x 256 threads,
// cluster of 4, 8 batch rows per cluster, two-pass dots, h/c carry via global.
// NEW: wout / wbf flags skip dead stores (f32 out for layers 0-3; bf16 hi/lo
// for layer 4) — pure work removal, no structural change.
// ============================================================================
__global__ void __launch_bounds__(256, 2) __cluster_dims__(4, 1, 1)
lstm_rec(const float* __restrict__ pre,
         float* __restrict__ out,
         const float* __restrict__ Whh,
         __nv_bfloat16* __restrict__ gh,
         __nv_bfloat16* __restrict__ gl,
         float* __restrict__ hst,
         float* __restrict__ cst,
         int first, int wout, int wbf)
{
    __shared__ float gbuf[8][8][128];
    __shared__ __align__(16) float hs[2][8][128];

    const int tid = threadIdx.x, lane = tid & 31, w = tid >> 5;
    uint32_t rank;
    asm("mov.u32 %0, %%cluster_ctarank;" : "=r"(rank));
    const int sl = (w + 2 * (int)rank) & 7;
    const int k0 = sl * 16;
    const bool own = (w < 2);
    const int b0 = (blockIdx.x >> 2) * 8;

    unsigned long long Wr[4][8];
#pragma unroll
    for (int g = 0; g < 4; g++) {
        const int grow = g * H_D + (int)rank * 32 + lane;
#pragma unroll
        for (int i = 0; i < 8; i++)
            Wr[g][i] = pack2(Whh[grow * H_D + k0 + 2 * i],
                             Whh[grow * H_D + k0 + 2 * i + 1]);
    }

    const int ob = tid >> 5, oj = tid & 31;
    const int jglob = (int)rank * 32 + oj;
    float c_state = 0.0f;
    const float* pre_p = pre + ((size_t)b0 + ob) * G4 + jglob;
    float* out_p = out + ((size_t)b0 + ob) * H_D + jglob;
    __nv_bfloat16* gh_p = gh + ((size_t)b0 + ob) * H_D + jglob;
    __nv_bfloat16* gl_p = gl + ((size_t)b0 + ob) * H_D + jglob;

    if (first) {
        for (int i = tid; i < 8 * H_D; i += 256) hs[0][i >> 7][i & 127] = 0.0f;
    } else {
        for (int i = tid; i < 8 * H_D; i += 256)
            hs[0][i >> 7][i & 127] = hst[(size_t)(b0 + (i >> 7)) * H_D + (i & 127)];
        c_state = cst[(size_t)(b0 + ob) * H_D + jglob];
    }
    __syncthreads();
    asm volatile("barrier.cluster.arrive.aligned;" ::: "memory");

    for (int tl = 0; tl < TC; tl++) {
        const int cur = tl & 1, nxt = cur ^ 1;
        const bool more = (tl + 1 < TC);

        const float p0 = pre_p[0],   p1 = pre_p[128];
        const float p2 = pre_p[256], p3 = pre_p[384];
        pre_p += (size_t)B_SZ * G4;

        if (own) {
#pragma unroll
            for (int pass = 0; pass < 2; pass++) {
                unsigned long long acc[4][4];
#pragma unroll
                for (int g = 0; g < 4; g++)
#pragma unroll
                    for (int b = 0; b < 4; b++) acc[g][b] = 0ull;
#pragma unroll
                for (int kk = 0; kk < 4; kk++) {
                    ulonglong2 v[4];
#pragma unroll
                    for (int b = 0; b < 4; b++)
                        v[b] = *(const ulonglong2*)(&hs[cur][pass * 4 + b][k0 + 4 * kk]);
#pragma unroll
                    for (int g = 0; g < 4; g++)
#pragma unroll
                        for (int b = 0; b < 4; b++) {
                            fma2(acc[g][b], v[b].x, Wr[g][2 * kk]);
                            fma2(acc[g][b], v[b].y, Wr[g][2 * kk + 1]);
                        }
                }
#pragma unroll
                for (int g = 0; g < 4; g++)
#pragma unroll
                    for (int b = 0; b < 4; b++)
                        gbuf[sl][pass * 4 + b][g * 32 + lane] = sum2(acc[g][b]);
            }
        }

        asm volatile("barrier.cluster.wait.aligned;" ::: "memory");

        if (!own) {
#pragma unroll
            for (int pass = 0; pass < 2; pass++) {
                unsigned long long acc[4][4];
#pragma unroll
                for (int g = 0; g < 4; g++)
#pragma unroll
                    for (int b = 0; b < 4; b++) acc[g][b] = 0ull;
#pragma unroll
                for (int kk = 0; kk < 4; kk++) {
                    ulonglong2 v[4];
#pragma unroll
                    for (int b = 0; b < 4; b++)
                        v[b] = *(const ulonglong2*)(&hs[cur][pass * 4 + b][k0 + 4 * kk]);
#pragma unroll
                    for (int g = 0; g < 4; g++)
#pragma unroll
                        for (int b = 0; b < 4; b++) {
                            fma2(acc[g][b], v[b].x, Wr[g][2 * kk]);
                            fma2(acc[g][b], v[b].y, Wr[g][2 * kk + 1]);
                        }
                }
#pragma unroll
                for (int g = 0; g < 4; g++)
#pragma unroll
                    for (int b = 0; b < 4; b++)
                        gbuf[sl][pass * 4 + b][g * 32 + lane] = sum2(acc[g][b]);
            }
        }

        __syncthreads();

        {
            float gv0 = p0, gv1 = p1, gv2 = p2, gv3 = p3;
#pragma unroll
            for (int q = 0; q < 8; q++) {
                gv0 += gbuf[q][ob][oj];
                gv1 += gbuf[q][ob][32 + oj];
                gv2 += gbuf[q][ob][64 + oj];
                gv3 += gbuf[q][ob][96 + oj];
            }
            const float ig = fsig(gv0), fg = fsig(gv1);
            const float gg = ftanh(gv2), og = fsig(gv3);
            c_state = fg * c_state + ig * gg;
            const float h = og * ftanh(c_state);

            if (more) {
                float* hp = &hs[nxt][ob][jglob];
                *hp = h;
                const uint32_t la = (uint32_t)__cvta_generic_to_shared(hp);
#pragma unroll
                for (int pr = 0; pr < 4; pr++)
                    if (pr != (int)rank)
                        asm volatile("{ .reg .b32 ra;\n\t"
                            "mapa.shared::cluster.u32 ra, %0, %1;\n\t"
                            "st.shared::cluster.f32 [ra], %2; }"
                            :: "r"(la), "r"(pr), "f"(h) : "memory");
            } else {
                hst[(size_t)(b0 + ob) * H_D + jglob] = h;
                cst[(size_t)(b0 + ob) * H_D + jglob] = c_state;
            }
            if (wout) {                                   // final layer only
                *out_p = h;
                out_p += (size_t)B_SZ * H_D;
            }
            if (wbf) {                                    // layers 0-3 only
                const __nv_bfloat16 hh = __float2bfloat16_rn(h);
                *gh_p = hh;
                *gl_p = __float2bfloat16_rn(h - __bfloat162float(hh));
                gh_p += (size_t)B_SZ * H_D;
                gl_p += (size_t)B_SZ * H_D;
            }
        }

        if (more)
            asm volatile("barrier.cluster.arrive.aligned;" ::: "memory");
        __syncthreads();
    }
}

// ============================================================================
// stream/event DAG (R13 config: same-priority streams)
// ============================================================================
struct DagRes {
    cudaStream_t ls[5], lp[5];
    cudaEvent_t fork, evP[5][NCH], evR[5][NCH], tail[10];
    DagRes() {
        for (int l = 0; l < 5; l++) {
            cudaStreamCreateWithFlags(&ls[l], cudaStreamNonBlocking);
            cudaStreamCreateWithFlags(&lp[l], cudaStreamNonBlocking);
        }
        cudaEventCreateWithFlags(&fork, cudaEventDisableTiming);
        for (int l = 0; l < 5; l++)
            for (int c = 0; c < NCH; c++) {
                cudaEventCreateWithFlags(&evP[l][c], cudaEventDisableTiming);
                cudaEventCreateWithFlags(&evR[l][c], cudaEventDisableTiming);
            }
        for (int i = 0; i < 10; i++)
            cudaEventCreateWithFlags(&tail[i], cudaEventDisableTiming);
    }
};
static DagRes g_dag;

extern "C" void kernel_launch(void* const* d_in, const int* in_sizes, int n_in,
                              void* d_out, int out_size) {
    const float* x     = (const float*)d_in[0];
    const float* Wih0  = (const float*)d_in[1];
    const float* Wrest = (const float*)d_in[2];
    const float* Whh   = (const float*)d_in[3];
    const float* bih   = (const float*)d_in[4];
    const float* bhh   = (const float*)d_in[5];
    float* out = (float*)d_out;

    float *bufA, *preb, *hst, *cst;
    __nv_bfloat16 *actH, *actL, *xh, *xl, *wh, *wl;
    cudaGetSymbolAddress((void**)&bufA, g_bufA);
    cudaGetSymbolAddress((void**)&preb, g_preb);
    cudaGetSymbolAddress((void**)&actH, g_actH);
    cudaGetSymbolAddress((void**)&actL, g_actL);
    cudaGetSymbolAddress((void**)&xh, g_xh);
    cudaGetSymbolAddress((void**)&xl, g_xl);
    cudaGetSymbolAddress((void**)&wh, g_wh);
    cudaGetSymbolAddress((void**)&wl, g_wl);
    cudaGetSymbolAddress((void**)&hst, g_hst);
    cudaGetSymbolAddress((void**)&cst, g_cst);

    const int SP64  = 512 + 64 * 72  * 2 * 2 + 64  * 136 * 2 * 2;  //  53760
    const int SP128 = 512 + 64 * 136 * 2 * 2 + 128 * 136 * 2 * 2;  // 104960
    cudaFuncSetAttribute(pregemm<64>,
        cudaFuncAttributeMaxDynamicSharedMemorySize, SP64);
    cudaFuncSetAttribute(pregemm<128>,
        cudaFuncAttributeMaxDynamicSharedMemorySize, SP128);

    DagRes& D = g_dag;

    // ---- upfront conversions on the capture stream ----
    xconvert<<<TB * IN_D / 4 / 256, 256>>>(x, xh, xl, TB * IN_D / 4);
    wconvert<<<64 * G4 / 256, 256>>>(Wih0, wh, wl, 64);
    for (int l = 1; l < 5; l++)
        wconvert<<<128 * G4 / 256, 256>>>(
            Wrest + (size_t)(l - 1) * G4 * H_D,
            wh + (size_t)l * H_D * G4, wl + (size_t)l * H_D * G4, 128);

    cudaEventRecord(D.fork, 0);
    for (int l = 0; l < 5; l++) {
        cudaStreamWaitEvent(D.lp[l], D.fork, 0);
        cudaStreamWaitEvent(D.ls[l], D.fork, 0);
    }

    // ---- pipelined layer-chunk DAG ----
    for (int c = 0; c < NCH; c++) {
        for (int l = 0; l < 5; l++) {
            const size_t rowoff = (size_t)c * CHROWS;
            float* pre_c = preb + ((size_t)l * TB + rowoff) * G4;

            if (l > 0) cudaStreamWaitEvent(D.lp[l], D.evR[l - 1][c], 0);
            if (l == 0) {
                pregemm<64><<<CHROWS / 64 * 4, 256, SP64, D.lp[0]>>>(
                    xh + rowoff * IN_D, xl + rowoff * IN_D,
                    wh, wl, bih, bhh, pre_c);
            } else {
                const size_t aoff = ((size_t)(l - 1) * TB + rowoff) * H_D;
                pregemm<128><<<CHROWS / 64 * 4, 256, SP128, D.lp[l]>>>(
                    actH + aoff, actL + aoff,
                    wh + (size_t)l * H_D * G4, wl + (size_t)l * H_D * G4,
                    bih + (size_t)l * G4, bhh + (size_t)l * G4, pre_c);
            }
            cudaEventRecord(D.evP[l][c], D.lp[l]);

            cudaStreamWaitEvent(D.ls[l], D.evP[l][c], 0);
            float* out_c = (l == 4) ? out + rowoff * H_D
                                    : bufA + rowoff * H_D;
            const size_t goff = ((size_t)l * TB + rowoff) * H_D;
            lstm_rec<<<128, 256, 0, D.ls[l]>>>(
                pre_c, out_c, Whh + (size_t)l * G4 * H_D,
                actH + goff, actL + goff,
                hst + (size_t)l * B_SZ * H_D, cst + (size_t)l * B_SZ * H_D,
                (c == 0) ? 1 : 0,
                (l == 4) ? 1 : 0,      // wout: final layer only
                (l == 4) ? 0 : 1);     // wbf: feeds next layer only
            cudaEventRecord(D.evR[l][c], D.ls[l]);
        }
    }

    // ---- join all side streams back to the capture stream ----
    for (int l = 0; l < 5; l++) {
        cudaEventRecord(D.tail[l], D.ls[l]);
        cudaStreamWaitEvent(0, D.tail[l], 0);
        cudaEventRecord(D.tail[5 + l], D.lp[l]);
        cudaStreamWaitEvent(0, D.tail[5 + l], 0);
    }
}